// round 3
// baseline (speedup 1.0000x reference)
#include <cuda_runtime.h>

// Problem constants (from reference setup_inputs):
//   x:        (16, 2048, 256) fp32  -> N = 32768 rows, D = 256
//   codebook: (4096, 256)     fp32  -> K = 4096 codes
// Output: quantized_st (N*D floats) followed by scalar loss.
#define N_ROWS 32768
#define D_DIM  256
#define K_CODES 4096

// ---------------- device scratch (no allocations allowed) ----------------
__device__ unsigned long long g_best[N_ROWS];   // packed (fkey(score)<<32)|~code
__device__ float g_csq[K_CODES];                // ||c_k||^2
__device__ float g_partial[N_ROWS / 8];         // per-block loss partials (4096)

// monotonic float -> uint key (order-preserving for all finite floats)
__device__ __forceinline__ unsigned int fkey(float f) {
    unsigned int u = __float_as_uint(f);
    return (u & 0x80000000u) ? ~u : (u | 0x80000000u);
}

// ---------------- kernel 1: reset argmax scratch ----------------
__global__ void init_kernel() {
    int i = blockIdx.x * blockDim.x + threadIdx.x;
    if (i < N_ROWS) g_best[i] = 0ull;   // below fkey of any finite float
}

// ---------------- kernel 2: codebook squared norms ----------------
__global__ void csq_kernel(const float* __restrict__ cb) {
    int warp = (blockIdx.x * blockDim.x + threadIdx.x) >> 5;
    int lane = threadIdx.x & 31;
    if (warp >= K_CODES) return;
    const float4* row = (const float4*)(cb + (size_t)warp * D_DIM);
    float s = 0.f;
    #pragma unroll
    for (int i = lane; i < D_DIM / 4; i += 32) {
        float4 v = row[i];
        s += v.x * v.x + v.y * v.y + v.z * v.z + v.w * v.w;
    }
    #pragma unroll
    for (int o = 16; o; o >>= 1) s += __shfl_down_sync(0xffffffffu, s, o);
    if (lane == 0) g_csq[warp] = s;
}

// ---------------- kernel 3: score GEMM + argmax epilogue ----------------
// Block tile: BM=128 rows x BN=128 codes, BK=16 over D.
// 256 threads, each computes an 8x8 microtile.
// score(m, k) = dot(x_m, c_k) - 0.5*||c_k||^2  (argmax == argmin of sq-dist)
#define BM 128
#define BN 128
#define BK 16

__global__ __launch_bounds__(256, 2)
void score_kernel(const float* __restrict__ X, const float* __restrict__ C) {
    __shared__ float As[BK][BM];
    __shared__ float Bs[BK][BN];

    const int m0 = blockIdx.y * BM;
    const int n0 = blockIdx.x * BN;
    const int tid = threadIdx.x;
    const int tx = tid & 15;        // 0..15 -> 8 codes each
    const int ty = tid >> 4;        // 0..15 -> 8 rows each

    float acc[8][8];
    #pragma unroll
    for (int i = 0; i < 8; i++)
        #pragma unroll
        for (int j = 0; j < 8; j++) acc[i][j] = 0.f;

    for (int dt = 0; dt < D_DIM; dt += BK) {
        // Load A (x tile) and B (codebook tile), transposed into smem.
        // 512 float4 per tile; each thread does 2.
        #pragma unroll
        for (int l = 0; l < 2; l++) {
            int idx = tid + l * 256;          // 0..511
            int row = idx >> 2;               // 0..127
            int d4  = (idx & 3) * 4;          // 0,4,8,12
            float4 v = *(const float4*)(X + (size_t)(m0 + row) * D_DIM + dt + d4);
            As[d4 + 0][row] = v.x; As[d4 + 1][row] = v.y;
            As[d4 + 2][row] = v.z; As[d4 + 3][row] = v.w;
            float4 w = *(const float4*)(C + (size_t)(n0 + row) * D_DIM + dt + d4);
            Bs[d4 + 0][row] = w.x; Bs[d4 + 1][row] = w.y;
            Bs[d4 + 2][row] = w.z; Bs[d4 + 3][row] = w.w;
        }
        __syncthreads();

        #pragma unroll
        for (int kk = 0; kk < BK; kk++) {
            float a[8], b[8];
            *(float4*)(a)     = *(const float4*)&As[kk][ty * 8];
            *(float4*)(a + 4) = *(const float4*)&As[kk][ty * 8 + 4];
            *(float4*)(b)     = *(const float4*)&Bs[kk][tx * 8];
            *(float4*)(b + 4) = *(const float4*)&Bs[kk][tx * 8 + 4];
            #pragma unroll
            for (int i = 0; i < 8; i++)
                #pragma unroll
                for (int j = 0; j < 8; j++)
                    acc[i][j] = fmaf(a[i], b[j], acc[i][j]);
        }
        __syncthreads();
    }

    // Epilogue: per-row argmax over this block's 128 codes, then global atomicMax.
    #pragma unroll
    for (int i = 0; i < 8; i++) {
        int row = m0 + ty * 8 + i;
        float best = -3.4e38f;
        int bidx = 0x7fffffff;
        #pragma unroll
        for (int j = 0; j < 8; j++) {
            int code = n0 + tx * 8 + j;
            float s = acc[i][j] - 0.5f * g_csq[code];
            if (s > best || (s == best && code < bidx)) { best = s; bidx = code; }
        }
        // reduce across the 16 lanes sharing this row group (same ty)
        #pragma unroll
        for (int o = 8; o; o >>= 1) {
            float ov = __shfl_down_sync(0xffffffffu, best, o, 16);
            int   oi = __shfl_down_sync(0xffffffffu, bidx, o, 16);
            if (ov > best || (ov == best && oi < bidx)) { best = ov; bidx = oi; }
        }
        if (tx == 0) {
            unsigned long long p =
                ((unsigned long long)fkey(best) << 32) | (unsigned int)(~bidx);
            atomicMax(&g_best[row], p);
        }
    }
}

// ---------------- kernel 4: gather + straight-through + loss partials ----------------
// One warp per row; 8 rows per 256-thread block.
__global__ void gather_kernel(const float* __restrict__ X,
                              const float* __restrict__ C,
                              float* __restrict__ out) {
    __shared__ float wsum[8];
    int warp = threadIdx.x >> 5;
    int lane = threadIdx.x & 31;
    int row = blockIdx.x * 8 + warp;

    float lsum = 0.f;
    if (row < N_ROWS) {
        int code = (int)(~((unsigned int)g_best[row])) & (K_CODES - 1);
        const float4* xr = (const float4*)(X + (size_t)row * D_DIM);
        const float4* cr = (const float4*)(C + (size_t)code * D_DIM);
        float4* orow = (float4*)(out + (size_t)row * D_DIM);
        #pragma unroll
        for (int i = lane; i < D_DIM / 4; i += 32) {
            float4 xv = xr[i];
            float4 cv = cr[i];
            float4 q;
            float dx = cv.x - xv.x; q.x = xv.x + dx; lsum += dx * dx;
            float dy = cv.y - xv.y; q.y = xv.y + dy; lsum += dy * dy;
            float dz = cv.z - xv.z; q.z = xv.z + dz; lsum += dz * dz;
            float dw = cv.w - xv.w; q.w = xv.w + dw; lsum += dw * dw;
            orow[i] = q;
        }
    }
    #pragma unroll
    for (int o = 16; o; o >>= 1) lsum += __shfl_down_sync(0xffffffffu, lsum, o);
    if (lane == 0) wsum[warp] = lsum;
    __syncthreads();
    if (threadIdx.x == 0) {
        float s = 0.f;
        #pragma unroll
        for (int i = 0; i < 8; i++) s += wsum[i];
        g_partial[blockIdx.x] = s;
    }
}

// ---------------- kernel 5: deterministic final loss reduction ----------------
// loss = q_latent + 0.25*e_latent = 1.25 * mean((quantized - x)^2)
__global__ void loss_kernel(float* __restrict__ out, int nPartial, int lossPos) {
    __shared__ float sm[256];
    float s = 0.f;
    for (int i = threadIdx.x; i < nPartial; i += 256) s += g_partial[i];
    sm[threadIdx.x] = s;
    __syncthreads();
    for (int o = 128; o; o >>= 1) {
        if (threadIdx.x < o) sm[threadIdx.x] += sm[threadIdx.x + o];
        __syncthreads();
    }
    if (threadIdx.x == 0)
        out[lossPos] = 1.25f * sm[0] / (float)((long long)N_ROWS * D_DIM);
}

extern "C" void kernel_launch(void* const* d_in, const int* in_sizes, int n_in,
                              void* d_out, int out_size) {
    const float* X = (const float*)d_in[0];   // (16, 2048, 256) fp32
    const float* C = (const float*)d_in[1];   // (4096, 256) fp32
    float* out = (float*)d_out;

    init_kernel<<<(N_ROWS + 255) / 256, 256>>>();
    csq_kernel<<<(K_CODES * 32 + 255) / 256, 256>>>(C);

    dim3 grid(K_CODES / BN, N_ROWS / BM);     // (32, 256)
    score_kernel<<<grid, 256>>>(X, C);

    gather_kernel<<<N_ROWS / 8, 256>>>(X, C, out);
    loss_kernel<<<1, 256>>>(out, N_ROWS / 8, out_size - 1);
}

// round 7
// speedup vs baseline: 1.6788x; 1.6788x over previous
#include <cuda_runtime.h>
#include <cuda_bf16.h>

// Problem constants:
//   x:        (16, 2048, 256) fp32  -> N = 32768 rows, D = 256
//   codebook: (4096, 256)     fp32  -> K = 4096 codes
// Output: quantized_st (N*D floats) followed by scalar loss.
#define N_ROWS 32768
#define D_DIM  256
#define K_CODES 4096
#define CAP 32                 // max rescue candidates per row
#define MARGIN 1e-3f           // approx-score rescue margin (>> split-bf16 error)

// ---------------- device scratch (no allocations allowed) ----------------
__device__ __align__(16) __nv_bfloat16 g_Xhi[N_ROWS * D_DIM];
__device__ __align__(16) __nv_bfloat16 g_Xlo[N_ROWS * D_DIM];
__device__ __align__(16) __nv_bfloat16 g_Chi[K_CODES * D_DIM];
__device__ __align__(16) __nv_bfloat16 g_Clo[K_CODES * D_DIM];
__device__ int   g_cands[N_ROWS * CAP];   // rescue candidate codes per row
__device__ int   g_candcnt[N_ROWS];
__device__ float g_csq[K_CODES];          // ||c_k||^2 (exact fp32)
__device__ float g_partial[N_ROWS / 8];   // per-block loss partials

// ---------------- split-bf16 conversion kernels ----------------
__global__ void cvt_x_kernel(const float* __restrict__ src) {
    int i = blockIdx.x * blockDim.x + threadIdx.x;
    if (i >= N_ROWS * D_DIM / 4) return;
    float4 v = ((const float4*)src)[i];
    __nv_bfloat16 h0 = __float2bfloat16(v.x), h1 = __float2bfloat16(v.y);
    __nv_bfloat16 h2 = __float2bfloat16(v.z), h3 = __float2bfloat16(v.w);
    __nv_bfloat16 l0 = __float2bfloat16(v.x - __bfloat162float(h0));
    __nv_bfloat16 l1 = __float2bfloat16(v.y - __bfloat162float(h1));
    __nv_bfloat16 l2 = __float2bfloat16(v.z - __bfloat162float(h2));
    __nv_bfloat16 l3 = __float2bfloat16(v.w - __bfloat162float(h3));
    __nv_bfloat162* H = (__nv_bfloat162*)g_Xhi;
    __nv_bfloat162* L = (__nv_bfloat162*)g_Xlo;
    H[2 * i]     = __halves2bfloat162(h0, h1);
    H[2 * i + 1] = __halves2bfloat162(h2, h3);
    L[2 * i]     = __halves2bfloat162(l0, l1);
    L[2 * i + 1] = __halves2bfloat162(l2, l3);
}

__global__ void cvt_c_kernel(const float* __restrict__ src) {
    int i = blockIdx.x * blockDim.x + threadIdx.x;
    if (i >= K_CODES * D_DIM / 4) return;
    float4 v = ((const float4*)src)[i];
    __nv_bfloat16 h0 = __float2bfloat16(v.x), h1 = __float2bfloat16(v.y);
    __nv_bfloat16 h2 = __float2bfloat16(v.z), h3 = __float2bfloat16(v.w);
    __nv_bfloat16 l0 = __float2bfloat16(v.x - __bfloat162float(h0));
    __nv_bfloat16 l1 = __float2bfloat16(v.y - __bfloat162float(h1));
    __nv_bfloat16 l2 = __float2bfloat16(v.z - __bfloat162float(h2));
    __nv_bfloat16 l3 = __float2bfloat16(v.w - __bfloat162float(h3));
    __nv_bfloat162* H = (__nv_bfloat162*)g_Chi;
    __nv_bfloat162* L = (__nv_bfloat162*)g_Clo;
    H[2 * i]     = __halves2bfloat162(h0, h1);
    H[2 * i + 1] = __halves2bfloat162(h2, h3);
    L[2 * i]     = __halves2bfloat162(l0, l1);
    L[2 * i + 1] = __halves2bfloat162(l2, l3);
}

// ---------------- codebook squared norms (exact fp32) ----------------
__global__ void csq_kernel(const float* __restrict__ cb) {
    int warp = (blockIdx.x * blockDim.x + threadIdx.x) >> 5;
    int lane = threadIdx.x & 31;
    if (warp >= K_CODES) return;
    const float4* row = (const float4*)(cb + (size_t)warp * D_DIM);
    float s = 0.f;
    #pragma unroll
    for (int i = lane; i < D_DIM / 4; i += 32) {
        float4 v = row[i];
        s += v.x * v.x + v.y * v.y + v.z * v.z + v.w * v.w;
    }
    #pragma unroll
    for (int o = 16; o; o >>= 1) s += __shfl_down_sync(0xffffffffu, s, o);
    if (lane == 0) g_csq[warp] = s;
}

// ---------------- tensor-core score GEMM + margin-candidate epilogue ------
// Each block: 128 rows x ALL 4096 codes. 3-pass split-bf16 MMA:
//   score ~= x_hi.c_hi + x_hi.c_lo + x_lo.c_hi - 0.5*||c||^2
// Per-row running max in smem; every code within MARGIN of the running max
// is appended to a per-row candidate list for exact fp32 rescoring later.
#define LDA 264               // A smem row stride (bf16 elems)
#define LDB 40                // B smem row stride
#define SM_A 0
#define SM_B    (2 * 128 * LDA * 2)          // 135168
#define SM_CSQ  (SM_B + 2 * 128 * LDB * 2)   // 155648
#define SM_STG  (SM_CSQ + 512)               // 156160 (256 floats)
#define SM_RUN  (SM_STG + 1024)              // 157184 (128 floats)
#define SM_CNT  (SM_RUN + 512)               // 157696 (128 ints)
#define SMEM_TOTAL (SM_CNT + 512)            // 158208

__device__ __forceinline__ unsigned su32(const void* p) {
    return (unsigned)__cvta_generic_to_shared(p);
}
__device__ __forceinline__ void ldsm4(unsigned a, unsigned& r0, unsigned& r1,
                                      unsigned& r2, unsigned& r3) {
    asm volatile("ldmatrix.sync.aligned.m8n8.x4.shared.b16 {%0,%1,%2,%3}, [%4];"
                 : "=r"(r0), "=r"(r1), "=r"(r2), "=r"(r3) : "r"(a));
}
__device__ __forceinline__ void mma16816(float* d, const unsigned* a,
                                         unsigned b0, unsigned b1) {
    asm volatile(
        "mma.sync.aligned.m16n8k16.row.col.f32.bf16.bf16.f32 "
        "{%0,%1,%2,%3},{%4,%5,%6,%7},{%8,%9},{%0,%1,%2,%3};"
        : "+f"(d[0]), "+f"(d[1]), "+f"(d[2]), "+f"(d[3])
        : "r"(a[0]), "r"(a[1]), "r"(a[2]), "r"(a[3]), "r"(b0), "r"(b1));
}
__device__ __forceinline__ bool better(float s, int i, float os, int oi) {
    return (s > os) || (s == os && i < oi);
}

__global__ __launch_bounds__(256)
void score_kernel() {
    extern __shared__ char smem[];
    __nv_bfloat16* As = (__nv_bfloat16*)(smem + SM_A);
    __nv_bfloat16* Bs = (__nv_bfloat16*)(smem + SM_B);
    float* csqs  = (float*)(smem + SM_CSQ);
    float* stage = (float*)(smem + SM_STG);
    float* run   = (float*)(smem + SM_RUN);
    int*   cnt   = (int*)(smem + SM_CNT);

    const int tid  = threadIdx.x;
    const int lane = tid & 31;
    const int warp = tid >> 5;
    const int wm = warp & 3;      // 0..3 -> row block of 32
    const int wn = warp >> 2;     // 0..1 -> col block of 64
    const int m0 = blockIdx.x * 128;

    // Load A (hi+lo, full K=256) into smem once.
    {
        const uint4* srcH = (const uint4*)(g_Xhi + (size_t)m0 * D_DIM);
        const uint4* srcL = (const uint4*)(g_Xlo + (size_t)m0 * D_DIM);
        #pragma unroll
        for (int i = 0; i < 16; i++) {
            int idx = tid + i * 256;      // 0..4095 (128 rows x 32 quads)
            int row = idx >> 5, kq = idx & 31;
            *(uint4*)(As + row * LDA + kq * 8) = srcH[row * 32 + kq];
            *(uint4*)(As + 128 * LDA + row * LDA + kq * 8) = srcL[row * 32 + kq];
        }
    }
    if (tid < 128) { run[tid] = -3.4e38f; cnt[tid] = 0; }
    __syncthreads();

    #pragma unroll 1
    for (int nt128 = 0; nt128 < K_CODES / 128; nt128++) {
        const int n0 = nt128 * 128;
        float acc[2][8][4];
        #pragma unroll
        for (int a = 0; a < 2; a++)
            #pragma unroll
            for (int b = 0; b < 8; b++)
                #pragma unroll
                for (int c = 0; c < 4; c++) acc[a][b][c] = 0.f;
        if (tid < 128) csqs[tid] = g_csq[n0 + tid];

        #pragma unroll 1
        for (int kc = 0; kc < 8; kc++) {
            // load B chunk (128 codes x 32 k, hi+lo)
            #pragma unroll
            for (int i = 0; i < 4; i++) {
                int idx = tid + i * 256;        // 0..1023
                int p = idx >> 9, rem = idx & 511;
                int row = rem >> 2, kq = rem & 3;
                const __nv_bfloat16* src = p ? g_Clo : g_Chi;
                *(uint4*)(Bs + p * 128 * LDB + row * LDB + kq * 8) =
                    *(const uint4*)(src + (size_t)(n0 + row) * D_DIM + kc * 32 + kq * 8);
            }
            __syncthreads();

            #pragma unroll
            for (int ks = 0; ks < 2; ks++) {
                unsigned ah[2][4], al[2][4];
                #pragma unroll
                for (int mi = 0; mi < 2; mi++) {
                    int arow = wm * 32 + mi * 16 + (lane & 15);
                    int acol = kc * 32 + ks * 16 + (lane >> 4) * 8;
                    ldsm4(su32(As + arow * LDA + acol),
                          ah[mi][0], ah[mi][1], ah[mi][2], ah[mi][3]);
                    ldsm4(su32(As + 128 * LDA + arow * LDA + acol),
                          al[mi][0], al[mi][1], al[mi][2], al[mi][3]);
                }
                #pragma unroll
                for (int nb = 0; nb < 4; nb++) {
                    int brow = wn * 64 + nb * 16 + (lane >> 4) * 8 + (lane & 7);
                    int bcol = ks * 16 + ((lane >> 3) & 1) * 8;
                    unsigned h0, h1, h2, h3, l0, l1, l2, l3;
                    ldsm4(su32(Bs + brow * LDB + bcol), h0, h1, h2, h3);
                    ldsm4(su32(Bs + 128 * LDB + brow * LDB + bcol), l0, l1, l2, l3);
                    #pragma unroll
                    for (int mi = 0; mi < 2; mi++) {
                        mma16816(acc[mi][nb * 2],     ah[mi], h0, h1);
                        mma16816(acc[mi][nb * 2],     ah[mi], l0, l1);
                        mma16816(acc[mi][nb * 2],     al[mi], h0, h1);
                        mma16816(acc[mi][nb * 2 + 1], ah[mi], h2, h3);
                        mma16816(acc[mi][nb * 2 + 1], ah[mi], l2, l3);
                        mma16816(acc[mi][nb * 2 + 1], al[mi], h2, h3);
                    }
                }
            }
            __syncthreads();
        }

        // ---- Epilogue part 1: per-row max over this tile's 128 codes ----
        #pragma unroll
        for (int mi = 0; mi < 2; mi++) {
            #pragma unroll
            for (int rh = 0; rh < 2; rh++) {
                float mx = -3.4e38f;
                #pragma unroll
                for (int nt = 0; nt < 8; nt++) {
                    #pragma unroll
                    for (int c = 0; c < 2; c++) {
                        int col = wn * 64 + nt * 8 + (lane & 3) * 2 + c;
                        float s = acc[mi][nt][rh * 2 + c] - 0.5f * csqs[col];
                        mx = fmaxf(mx, s);
                    }
                }
                #pragma unroll
                for (int m = 1; m <= 2; m <<= 1)
                    mx = fmaxf(mx, __shfl_xor_sync(0xffffffffu, mx, m));
                if ((lane & 3) == 0) {
                    int r = wm * 32 + mi * 16 + rh * 8 + (lane >> 2);
                    stage[wn * 128 + r] = mx;
                }
            }
        }
        __syncthreads();
        if (tid < 128)
            run[tid] = fmaxf(run[tid], fmaxf(stage[tid], stage[128 + tid]));
        __syncthreads();

        // ---- Epilogue part 2: append candidates within MARGIN of run max --
        #pragma unroll
        for (int mi = 0; mi < 2; mi++) {
            #pragma unroll
            for (int rh = 0; rh < 2; rh++) {
                int r = wm * 32 + mi * 16 + rh * 8 + (lane >> 2);
                float thresh = run[r] - MARGIN;
                #pragma unroll
                for (int nt = 0; nt < 8; nt++) {
                    #pragma unroll
                    for (int c = 0; c < 2; c++) {
                        int col = wn * 64 + nt * 8 + (lane & 3) * 2 + c;
                        float s = acc[mi][nt][rh * 2 + c] - 0.5f * csqs[col];
                        if (s >= thresh) {
                            int slot = atomicAdd(&cnt[r], 1);
                            if (slot < CAP)
                                g_cands[(size_t)(m0 + r) * CAP + slot] = n0 + col;
                        }
                    }
                }
            }
        }
        __syncthreads();
    }

    if (tid < 128) g_candcnt[m0 + tid] = min(cnt[tid], CAP);
}

// ---------------- gather: serial-fp32 rescore (round-3-exact arithmetic) ---
// One warp per row. Lane ci rescores candidate ci with a SERIAL fmaf chain
// over k = 0..255 in natural order — bit-identical to the round-3 SIMT GEMM
// accumulation that matched the reference — then warp-argmax via better().
__global__ void gather_kernel(const float* __restrict__ X,
                              const float* __restrict__ C,
                              float* __restrict__ out) {
    __shared__ float xs[8][D_DIM];
    __shared__ float wsum[8];
    int warp = threadIdx.x >> 5;
    int lane = threadIdx.x & 31;
    int row = blockIdx.x * 8 + warp;

    float lsum = 0.f;
    if (row < N_ROWS) {
        // Stage x row in smem (float4 x2 per lane).
        const float4* xr = (const float4*)(X + (size_t)row * D_DIM);
        float4* xsv = (float4*)xs[warp];
        xsv[lane] = xr[lane];
        xsv[lane + 32] = xr[lane + 32];
        __syncwarp();

        int ncand = g_candcnt[row];
        float bs = -3.4e38f;
        int bc = 0x7fffffff;
        if (lane < ncand) {
            int cd = g_cands[(size_t)row * CAP + lane];
            const float4* cr = (const float4*)(C + (size_t)cd * D_DIM);
            // Serial fmaf chain, k ascending (matches round-3 summation order).
            float d = 0.f;
            #pragma unroll 8
            for (int q = 0; q < D_DIM / 4; q++) {
                float4 cv = __ldg(cr + q);
                const float* xp = &xs[warp][q * 4];
                d = fmaf(xp[0], cv.x, d);
                d = fmaf(xp[1], cv.y, d);
                d = fmaf(xp[2], cv.z, d);
                d = fmaf(xp[3], cv.w, d);
            }
            bs = d - 0.5f * g_csq[cd];
            bc = cd;
        }
        // Warp argmax with the same strict total order as round 3.
        #pragma unroll
        for (int o = 16; o; o >>= 1) {
            float os = __shfl_xor_sync(0xffffffffu, bs, o);
            int   oc = __shfl_xor_sync(0xffffffffu, bc, o);
            if (better(os, oc, bs, bc)) { bs = os; bc = oc; }
        }
        int code = bc;

        const float4* cr = (const float4*)(C + (size_t)code * D_DIM);
        float4* orow = (float4*)(out + (size_t)row * D_DIM);
        #pragma unroll
        for (int h = 0; h < 2; h++) {
            float4 x4 = ((float4*)xs[warp])[lane + h * 32];
            float4 cv = cr[lane + h * 32];
            float4 q;
            float dx = cv.x - x4.x; q.x = x4.x + dx; lsum += dx * dx;
            float dy = cv.y - x4.y; q.y = x4.y + dy; lsum += dy * dy;
            float dz = cv.z - x4.z; q.z = x4.z + dz; lsum += dz * dz;
            float dw = cv.w - x4.w; q.w = x4.w + dw; lsum += dw * dw;
            orow[lane + h * 32] = q;
        }
    }
    #pragma unroll
    for (int o = 16; o; o >>= 1) lsum += __shfl_down_sync(0xffffffffu, lsum, o);
    if (lane == 0) wsum[warp] = lsum;
    __syncthreads();
    if (threadIdx.x == 0) {
        float s = 0.f;
        #pragma unroll
        for (int i = 0; i < 8; i++) s += wsum[i];
        g_partial[blockIdx.x] = s;
    }
}

// ---------------- final loss reduction ----------------
__global__ void loss_kernel(float* __restrict__ out, int nPartial, int lossPos) {
    __shared__ float sm[256];
    float s = 0.f;
    for (int i = threadIdx.x; i < nPartial; i += 256) s += g_partial[i];
    sm[threadIdx.x] = s;
    __syncthreads();
    for (int o = 128; o; o >>= 1) {
        if (threadIdx.x < o) sm[threadIdx.x] += sm[threadIdx.x + o];
        __syncthreads();
    }
    if (threadIdx.x == 0)
        out[lossPos] = 1.25f * sm[0] / (float)((long long)N_ROWS * D_DIM);
}

extern "C" void kernel_launch(void* const* d_in, const int* in_sizes, int n_in,
                              void* d_out, int out_size) {
    const float* X = (const float*)d_in[0];   // (16, 2048, 256) fp32
    const float* C = (const float*)d_in[1];   // (4096, 256) fp32
    float* out = (float*)d_out;

    cudaFuncSetAttribute(score_kernel,
                         cudaFuncAttributeMaxDynamicSharedMemorySize, SMEM_TOTAL);

    cvt_x_kernel<<<(N_ROWS * D_DIM / 4 + 255) / 256, 256>>>(X);
    cvt_c_kernel<<<(K_CODES * D_DIM / 4 + 255) / 256, 256>>>(C);
    csq_kernel<<<(K_CODES * 32 + 255) / 256, 256>>>(C);

    score_kernel<<<N_ROWS / 128, 256, SMEM_TOTAL>>>();

    gather_kernel<<<N_ROWS / 8, 256>>>(X, C, out);
    loss_kernel<<<1, 256>>>(out, N_ROWS / 8, out_size - 1);
}

// round 10
// speedup vs baseline: 4.5428x; 2.7060x over previous
#include <cuda_runtime.h>
#include <cuda_bf16.h>

// Problem constants:
//   x:        (16, 2048, 256) fp32  -> N = 32768 rows, D = 256
//   codebook: (4096, 256)     fp32  -> K = 4096 codes
// Output: quantized_st (N*D floats) followed by scalar loss.
#define N_ROWS 32768
#define D_DIM  256
#define K_CODES 4096
#define CAP 32                 // max rescue candidates per row
#define MARGIN 0.04f           // covers 2x max single-pass bf16 score error (~9e-3)

// ---------------- device scratch (no allocations allowed) ----------------
__device__ __align__(16) __nv_bfloat16 g_Xhi[N_ROWS * D_DIM];
__device__ __align__(16) __nv_bfloat16 g_Chi[K_CODES * D_DIM];
__device__ int   g_cands[N_ROWS * CAP];   // rescue candidate codes per row
__device__ int   g_candcnt[N_ROWS];
__device__ float g_csq[K_CODES];          // ||c_k||^2 (exact fp32)
__device__ float g_partial[N_ROWS / 8];   // per-block loss partials

// ---------------- bf16 conversion kernels (hi part only) ----------------
__global__ void cvt_x_kernel(const float* __restrict__ src) {
    int i = blockIdx.x * blockDim.x + threadIdx.x;
    if (i >= N_ROWS * D_DIM / 4) return;
    float4 v = ((const float4*)src)[i];
    __nv_bfloat162* H = (__nv_bfloat162*)g_Xhi;
    H[2 * i]     = __halves2bfloat162(__float2bfloat16(v.x), __float2bfloat16(v.y));
    H[2 * i + 1] = __halves2bfloat162(__float2bfloat16(v.z), __float2bfloat16(v.w));
}

__global__ void cvt_c_kernel(const float* __restrict__ src) {
    int i = blockIdx.x * blockDim.x + threadIdx.x;
    if (i >= K_CODES * D_DIM / 4) return;
    float4 v = ((const float4*)src)[i];
    __nv_bfloat162* H = (__nv_bfloat162*)g_Chi;
    H[2 * i]     = __halves2bfloat162(__float2bfloat16(v.x), __float2bfloat16(v.y));
    H[2 * i + 1] = __halves2bfloat162(__float2bfloat16(v.z), __float2bfloat16(v.w));
}

// ---------------- codebook squared norms (exact fp32) ----------------
__global__ void csq_kernel(const float* __restrict__ cb) {
    int warp = (blockIdx.x * blockDim.x + threadIdx.x) >> 5;
    int lane = threadIdx.x & 31;
    if (warp >= K_CODES) return;
    const float4* row = (const float4*)(cb + (size_t)warp * D_DIM);
    float s = 0.f;
    #pragma unroll
    for (int i = lane; i < D_DIM / 4; i += 32) {
        float4 v = row[i];
        s += v.x * v.x + v.y * v.y + v.z * v.z + v.w * v.w;
    }
    #pragma unroll
    for (int o = 16; o; o >>= 1) s += __shfl_down_sync(0xffffffffu, s, o);
    if (lane == 0) g_csq[warp] = s;
}

// ---------------- tensor-core score GEMM + margin-candidate epilogue ------
// Each block: 128 rows x ALL 4096 codes, single bf16 pass:
//   score ~= xhi . chi - 0.5*||c||^2     (error <~ 9e-3, << MARGIN)
// Per-row running max in smem; every code within MARGIN of the running max
// is appended to a per-row candidate list for exact fp32 rescoring later.
// B chunks are cp.async double-buffered; A (hi) resident in smem.
#define LDA 264               // A smem row stride (bf16 elems)
#define LDB 40                // B smem row stride
#define SM_A 0
#define SM_B     (128 * LDA * 2)             // 67584
#define B_BUF    (128 * LDB * 2)             // 10240 per buffer
#define SM_CSQ   (SM_B + 2 * B_BUF)          // 88064
#define SM_STG   (SM_CSQ + 512)              // 88576 (256 floats)
#define SM_RUN   (SM_STG + 1024)             // 89600 (128 floats)
#define SM_CNT   (SM_RUN + 512)              // 90112 (128 ints)
#define SMEM_TOTAL (SM_CNT + 512)            // 90624  -> 2 CTAs/SM

__device__ __forceinline__ unsigned su32(const void* p) {
    return (unsigned)__cvta_generic_to_shared(p);
}
__device__ __forceinline__ void ldsm4(unsigned a, unsigned& r0, unsigned& r1,
                                      unsigned& r2, unsigned& r3) {
    asm volatile("ldmatrix.sync.aligned.m8n8.x4.shared.b16 {%0,%1,%2,%3}, [%4];"
                 : "=r"(r0), "=r"(r1), "=r"(r2), "=r"(r3) : "r"(a));
}
__device__ __forceinline__ void mma16816(float* d, const unsigned* a,
                                         unsigned b0, unsigned b1) {
    asm volatile(
        "mma.sync.aligned.m16n8k16.row.col.f32.bf16.bf16.f32 "
        "{%0,%1,%2,%3},{%4,%5,%6,%7},{%8,%9},{%0,%1,%2,%3};"
        : "+f"(d[0]), "+f"(d[1]), "+f"(d[2]), "+f"(d[3])
        : "r"(a[0]), "r"(a[1]), "r"(a[2]), "r"(a[3]), "r"(b0), "r"(b1));
}
__device__ __forceinline__ void cpasync16(unsigned s, const void* g) {
    asm volatile("cp.async.cg.shared.global [%0], [%1], 16;" :: "r"(s), "l"(g));
}
__device__ __forceinline__ bool better(float s, int i, float os, int oi) {
    return (s > os) || (s == os && i < oi);
}

__global__ __launch_bounds__(256, 2)
void score_kernel() {
    extern __shared__ char smem[];
    __nv_bfloat16* As = (__nv_bfloat16*)(smem + SM_A);
    float* csqs  = (float*)(smem + SM_CSQ);
    float* stage = (float*)(smem + SM_STG);
    float* run   = (float*)(smem + SM_RUN);
    int*   cnt   = (int*)(smem + SM_CNT);

    const int tid  = threadIdx.x;
    const int lane = tid & 31;
    const int warp = tid >> 5;
    const int wm = warp & 3;      // 0..3 -> row block of 32
    const int wn = warp >> 2;     // 0..1 -> col block of 64
    const int m0 = blockIdx.x * 128;
    const unsigned sB = su32(smem + SM_B);

    // Prefetch B chunk (tile 0, kc 0) into buffer 0 via cp.async.
    {
        #pragma unroll
        for (int j = 0; j < 2; j++) {
            int idx = tid + j * 256;          // 0..511
            int row = idx >> 2, kq = idx & 3;
            cpasync16(sB + (row * LDB + kq * 8) * 2,
                      g_Chi + (size_t)row * D_DIM + kq * 8);
        }
        asm volatile("cp.async.commit_group;");
    }

    // Load A (hi, full K=256) into smem once.
    {
        const uint4* srcH = (const uint4*)(g_Xhi + (size_t)m0 * D_DIM);
        #pragma unroll
        for (int i = 0; i < 16; i++) {
            int idx = tid + i * 256;      // 0..4095 (128 rows x 32 quads)
            int row = idx >> 5, kq = idx & 31;
            *(uint4*)(As + row * LDA + kq * 8) = srcH[row * 32 + kq];
        }
    }
    if (tid < 128) { run[tid] = -3.4e38f; cnt[tid] = 0; }
    __syncthreads();

    int buf = 0;
    #pragma unroll 1
    for (int nt128 = 0; nt128 < K_CODES / 128; nt128++) {
        const int n0 = nt128 * 128;
        if (tid < 128) csqs[tid] = g_csq[n0 + tid];

        float acc[2][8][4];
        #pragma unroll
        for (int a = 0; a < 2; a++)
            #pragma unroll
            for (int b = 0; b < 8; b++)
                #pragma unroll
                for (int c = 0; c < 4; c++) acc[a][b][c] = 0.f;

        #pragma unroll 1
        for (int kc = 0; kc < 8; kc++) {
            // Issue prefetch of the next chunk into the other buffer.
            bool last = (nt128 == K_CODES / 128 - 1) && (kc == 7);
            if (!last) {
                int nn0 = (kc == 7) ? n0 + 128 : n0;
                int nkc = (kc == 7) ? 0 : kc + 1;
                unsigned dst = sB + (buf ^ 1) * B_BUF;
                #pragma unroll
                for (int j = 0; j < 2; j++) {
                    int idx = tid + j * 256;
                    int row = idx >> 2, kq = idx & 3;
                    cpasync16(dst + (row * LDB + kq * 8) * 2,
                              g_Chi + (size_t)(nn0 + row) * D_DIM + nkc * 32 + kq * 8);
                }
                asm volatile("cp.async.commit_group;");
                asm volatile("cp.async.wait_group 1;");
            } else {
                asm volatile("cp.async.wait_group 0;");
            }
            __syncthreads();

            const unsigned bufB = sB + buf * B_BUF;
            #pragma unroll
            for (int ks = 0; ks < 2; ks++) {
                unsigned ah[2][4];
                #pragma unroll
                for (int mi = 0; mi < 2; mi++) {
                    int arow = wm * 32 + mi * 16 + (lane & 15);
                    int acol = kc * 32 + ks * 16 + (lane >> 4) * 8;
                    ldsm4(su32(As + arow * LDA + acol),
                          ah[mi][0], ah[mi][1], ah[mi][2], ah[mi][3]);
                }
                #pragma unroll
                for (int nb = 0; nb < 4; nb++) {
                    int brow = wn * 64 + nb * 16 + (lane >> 4) * 8 + (lane & 7);
                    int bcol = ks * 16 + ((lane >> 3) & 1) * 8;
                    unsigned b0, b1, b2, b3;
                    ldsm4(bufB + (brow * LDB + bcol) * 2, b0, b1, b2, b3);
                    #pragma unroll
                    for (int mi = 0; mi < 2; mi++) {
                        mma16816(acc[mi][nb * 2],     ah[mi], b0, b1);
                        mma16816(acc[mi][nb * 2 + 1], ah[mi], b2, b3);
                    }
                }
            }
            __syncthreads();
            buf ^= 1;
        }

        // ---- Epilogue part 1: per-row max over this tile's 128 codes ----
        #pragma unroll
        for (int mi = 0; mi < 2; mi++) {
            #pragma unroll
            for (int rh = 0; rh < 2; rh++) {
                float mx = -3.4e38f;
                #pragma unroll
                for (int nt = 0; nt < 8; nt++) {
                    #pragma unroll
                    for (int c = 0; c < 2; c++) {
                        int col = wn * 64 + nt * 8 + (lane & 3) * 2 + c;
                        float s = acc[mi][nt][rh * 2 + c] - 0.5f * csqs[col];
                        mx = fmaxf(mx, s);
                    }
                }
                #pragma unroll
                for (int m = 1; m <= 2; m <<= 1)
                    mx = fmaxf(mx, __shfl_xor_sync(0xffffffffu, mx, m));
                if ((lane & 3) == 0) {
                    int r = wm * 32 + mi * 16 + rh * 8 + (lane >> 2);
                    stage[wn * 128 + r] = mx;
                }
            }
        }
        __syncthreads();
        if (tid < 128)
            run[tid] = fmaxf(run[tid], fmaxf(stage[tid], stage[128 + tid]));
        __syncthreads();

        // ---- Epilogue part 2: append candidates within MARGIN of run max --
        #pragma unroll
        for (int mi = 0; mi < 2; mi++) {
            #pragma unroll
            for (int rh = 0; rh < 2; rh++) {
                int r = wm * 32 + mi * 16 + rh * 8 + (lane >> 2);
                float thresh = run[r] - MARGIN;
                #pragma unroll
                for (int nt = 0; nt < 8; nt++) {
                    #pragma unroll
                    for (int c = 0; c < 2; c++) {
                        int col = wn * 64 + nt * 8 + (lane & 3) * 2 + c;
                        float s = acc[mi][nt][rh * 2 + c] - 0.5f * csqs[col];
                        if (s >= thresh) {
                            int slot = atomicAdd(&cnt[r], 1);
                            if (slot < CAP)
                                g_cands[(size_t)(m0 + r) * CAP + slot] = n0 + col;
                        }
                    }
                }
            }
        }
        __syncthreads();
    }

    if (tid < 128) g_candcnt[m0 + tid] = min(cnt[tid], CAP);
}

// ---------------- gather: serial-fp32 rescore (reference-exact arithmetic) -
// One warp per row. Lane ci rescores candidate ci with a SERIAL fmaf chain
// over k = 0..255 in natural order (proven bit-exact vs reference in R7),
// then warp-argmax via better().
__global__ void gather_kernel(const float* __restrict__ X,
                              const float* __restrict__ C,
                              float* __restrict__ out) {
    __shared__ float xs[8][D_DIM];
    __shared__ float wsum[8];
    int warp = threadIdx.x >> 5;
    int lane = threadIdx.x & 31;
    int row = blockIdx.x * 8 + warp;

    float lsum = 0.f;
    if (row < N_ROWS) {
        const float4* xr = (const float4*)(X + (size_t)row * D_DIM);
        float4* xsv = (float4*)xs[warp];
        xsv[lane] = xr[lane];
        xsv[lane + 32] = xr[lane + 32];
        __syncwarp();

        int ncand = g_candcnt[row];
        float bs = -3.4e38f;
        int bc = 0x7fffffff;
        if (lane < ncand) {
            int cd = g_cands[(size_t)row * CAP + lane];
            const float4* cr = (const float4*)(C + (size_t)cd * D_DIM);
            float d = 0.f;
            #pragma unroll 8
            for (int q = 0; q < D_DIM / 4; q++) {
                float4 cv = __ldg(cr + q);
                const float* xp = &xs[warp][q * 4];
                d = fmaf(xp[0], cv.x, d);
                d = fmaf(xp[1], cv.y, d);
                d = fmaf(xp[2], cv.z, d);
                d = fmaf(xp[3], cv.w, d);
            }
            bs = d - 0.5f * g_csq[cd];
            bc = cd;
        }
        #pragma unroll
        for (int o = 16; o; o >>= 1) {
            float os = __shfl_xor_sync(0xffffffffu, bs, o);
            int   oc = __shfl_xor_sync(0xffffffffu, bc, o);
            if (better(os, oc, bs, bc)) { bs = os; bc = oc; }
        }
        int code = bc;

        const float4* cr = (const float4*)(C + (size_t)code * D_DIM);
        float4* orow = (float4*)(out + (size_t)row * D_DIM);
        #pragma unroll
        for (int h = 0; h < 2; h++) {
            float4 x4 = ((float4*)xs[warp])[lane + h * 32];
            float4 cv = cr[lane + h * 32];
            float4 q;
            float dx = cv.x - x4.x; q.x = x4.x + dx; lsum += dx * dx;
            float dy = cv.y - x4.y; q.y = x4.y + dy; lsum += dy * dy;
            float dz = cv.z - x4.z; q.z = x4.z + dz; lsum += dz * dz;
            float dw = cv.w - x4.w; q.w = x4.w + dw; lsum += dw * dw;
            orow[lane + h * 32] = q;
        }
    }
    #pragma unroll
    for (int o = 16; o; o >>= 1) lsum += __shfl_down_sync(0xffffffffu, lsum, o);
    if (lane == 0) wsum[warp] = lsum;
    __syncthreads();
    if (threadIdx.x == 0) {
        float s = 0.f;
        #pragma unroll
        for (int i = 0; i < 8; i++) s += wsum[i];
        g_partial[blockIdx.x] = s;
    }
}

// ---------------- final loss reduction ----------------
__global__ void loss_kernel(float* __restrict__ out, int nPartial, int lossPos) {
    __shared__ float sm[256];
    float s = 0.f;
    for (int i = threadIdx.x; i < nPartial; i += 256) s += g_partial[i];
    sm[threadIdx.x] = s;
    __syncthreads();
    for (int o = 128; o; o >>= 1) {
        if (threadIdx.x < o) sm[threadIdx.x] += sm[threadIdx.x + o];
        __syncthreads();
    }
    if (threadIdx.x == 0)
        out[lossPos] = 1.25f * sm[0] / (float)((long long)N_ROWS * D_DIM);
}

extern "C" void kernel_launch(void* const* d_in, const int* in_sizes, int n_in,
                              void* d_out, int out_size) {
    const float* X = (const float*)d_in[0];   // (16, 2048, 256) fp32
    const float* C = (const float*)d_in[1];   // (4096, 256) fp32
    float* out = (float*)d_out;

    cudaFuncSetAttribute(score_kernel,
                         cudaFuncAttributeMaxDynamicSharedMemorySize, SMEM_TOTAL);

    cvt_x_kernel<<<(N_ROWS * D_DIM / 4 + 255) / 256, 256>>>(X);
    cvt_c_kernel<<<(K_CODES * D_DIM / 4 + 255) / 256, 256>>>(C);
    csq_kernel<<<(K_CODES * 32 + 255) / 256, 256>>>(C);

    score_kernel<<<N_ROWS / 128, 256, SMEM_TOTAL>>>();

    gather_kernel<<<N_ROWS / 8, 256>>>(X, C, out);
    loss_kernel<<<1, 256>>>(out, N_ROWS / 8, out_size - 1);
}

// round 15
// speedup vs baseline: 4.8046x; 1.0576x over previous
#include <cuda_runtime.h>
#include <cuda_bf16.h>

// Problem constants:
//   x:        (16, 2048, 256) fp32  -> N = 32768 rows, D = 256
//   codebook: (4096, 256)     fp32  -> K = 4096 codes
// Output: quantized_st (N*D floats) followed by scalar loss.
#define N_ROWS 32768
#define D_DIM  256
#define K_CODES 4096
#define CAP 32                 // max rescue candidates per row
#define MARGIN 0.04f           // covers 2x max single-pass bf16 score error (~9e-3)

// ---------------- device scratch (no allocations allowed) ----------------
__device__ __align__(16) __nv_bfloat16 g_Xhi[N_ROWS * D_DIM];
__device__ __align__(16) __nv_bfloat16 g_Chi[K_CODES * D_DIM];
__device__ int   g_cands[N_ROWS * CAP];   // rescue candidate codes per row
__device__ int   g_candcnt[N_ROWS];
__device__ float g_csq[K_CODES];          // ||c_k||^2 (exact fp32)
__device__ float g_partial[N_ROWS / 8];   // per-block loss partials

// ---------------- bf16 conversion kernels (hi part only) ----------------
__global__ void cvt_x_kernel(const float* __restrict__ src) {
    int i = blockIdx.x * blockDim.x + threadIdx.x;
    if (i >= N_ROWS * D_DIM / 4) return;
    float4 v = ((const float4*)src)[i];
    __nv_bfloat162* H = (__nv_bfloat162*)g_Xhi;
    H[2 * i]     = __halves2bfloat162(__float2bfloat16(v.x), __float2bfloat16(v.y));
    H[2 * i + 1] = __halves2bfloat162(__float2bfloat16(v.z), __float2bfloat16(v.w));
}

__global__ void cvt_c_kernel(const float* __restrict__ src) {
    int i = blockIdx.x * blockDim.x + threadIdx.x;
    if (i >= K_CODES * D_DIM / 4) return;
    float4 v = ((const float4*)src)[i];
    __nv_bfloat162* H = (__nv_bfloat162*)g_Chi;
    H[2 * i]     = __halves2bfloat162(__float2bfloat16(v.x), __float2bfloat16(v.y));
    H[2 * i + 1] = __halves2bfloat162(__float2bfloat16(v.z), __float2bfloat16(v.w));
}

// ---------------- codebook squared norms (exact fp32) ----------------
__global__ void csq_kernel(const float* __restrict__ cb) {
    int warp = (blockIdx.x * blockDim.x + threadIdx.x) >> 5;
    int lane = threadIdx.x & 31;
    if (warp >= K_CODES) return;
    const float4* row = (const float4*)(cb + (size_t)warp * D_DIM);
    float s = 0.f;
    #pragma unroll
    for (int i = lane; i < D_DIM / 4; i += 32) {
        float4 v = row[i];
        s += v.x * v.x + v.y * v.y + v.z * v.z + v.w * v.w;
    }
    #pragma unroll
    for (int o = 16; o; o >>= 1) s += __shfl_down_sync(0xffffffffu, s, o);
    if (lane == 0) g_csq[warp] = s;
}

// ---------------- tensor-core score GEMM + margin-candidate epilogue ------
// Each block: 128 rows x ALL 4096 codes, single bf16 pass:
//   score ~= xhi . chi - 0.5*||c||^2     (error <~ 9e-3, << MARGIN)
// Per-row running max in smem; every code within MARGIN of the running max
// is appended to a per-row candidate list for exact fp32 rescoring later.
// B chunks (128 codes x 64 k) are cp.async double-buffered; A resident.
#define LDA 264               // A smem row stride (bf16 elems)
#define LDB 72                // B smem row stride (64 k + 8 pad), conflict-free
#define SM_A 0
#define SM_B     (128 * LDA * 2)             // 67584
#define B_BUF    (128 * LDB * 2)             // 18432 per buffer
#define SM_CSQ   (SM_B + 2 * B_BUF)          // 104448
#define SM_STG   (SM_CSQ + 512)              // 104960 (256 floats)
#define SM_RUN   (SM_STG + 1024)             // 105984 (128 floats)
#define SM_CNT   (SM_RUN + 512)              // 106496 (128 ints)
#define SMEM_TOTAL (SM_CNT + 512)            // 107008 -> 2 CTAs/SM

__device__ __forceinline__ unsigned su32(const void* p) {
    return (unsigned)__cvta_generic_to_shared(p);
}
__device__ __forceinline__ void ldsm4(unsigned a, unsigned& r0, unsigned& r1,
                                      unsigned& r2, unsigned& r3) {
    asm volatile("ldmatrix.sync.aligned.m8n8.x4.shared.b16 {%0,%1,%2,%3}, [%4];"
                 : "=r"(r0), "=r"(r1), "=r"(r2), "=r"(r3) : "r"(a));
}
__device__ __forceinline__ void mma16816(float* d, const unsigned* a,
                                         unsigned b0, unsigned b1) {
    asm volatile(
        "mma.sync.aligned.m16n8k16.row.col.f32.bf16.bf16.f32 "
        "{%0,%1,%2,%3},{%4,%5,%6,%7},{%8,%9},{%0,%1,%2,%3};"
        : "+f"(d[0]), "+f"(d[1]), "+f"(d[2]), "+f"(d[3])
        : "r"(a[0]), "r"(a[1]), "r"(a[2]), "r"(a[3]), "r"(b0), "r"(b1));
}
__device__ __forceinline__ void cpasync16(unsigned s, const void* g) {
    asm volatile("cp.async.cg.shared.global [%0], [%1], 16;" :: "r"(s), "l"(g));
}
__device__ __forceinline__ bool better(float s, int i, float os, int oi) {
    return (s > os) || (s == os && i < oi);
}

// Load one B chunk: 128 codes x 64 k bf16 (1024 uint4; 4 per thread).
__device__ __forceinline__ void load_B_chunk(unsigned dst, int n0, int kbase, int tid) {
    #pragma unroll
    for (int j = 0; j < 4; j++) {
        int idx = tid + j * 256;          // 0..1023
        int row = idx >> 3, kq = idx & 7;
        cpasync16(dst + (unsigned)(row * LDB + kq * 8) * 2,
                  g_Chi + (size_t)(n0 + row) * D_DIM + kbase + kq * 8);
    }
}

__global__ __launch_bounds__(256, 2)
void score_kernel() {
    extern __shared__ char smem[];
    __nv_bfloat16* As = (__nv_bfloat16*)(smem + SM_A);
    float* csqs  = (float*)(smem + SM_CSQ);
    float* stage = (float*)(smem + SM_STG);
    float* run   = (float*)(smem + SM_RUN);
    int*   cnt   = (int*)(smem + SM_CNT);

    const int tid  = threadIdx.x;
    const int lane = tid & 31;
    const int warp = tid >> 5;
    const int wm = warp & 3;      // 0..3 -> row block of 32
    const int wn = warp >> 2;     // 0..1 -> col block of 64
    const int m0 = blockIdx.x * 128;
    const unsigned sB = su32(smem + SM_B);

    // Prefetch B chunk (tile 0, kc 0) into buffer 0 via cp.async.
    load_B_chunk(sB, 0, 0, tid);
    asm volatile("cp.async.commit_group;");

    // Load A (hi, full K=256) into smem once.
    {
        const uint4* srcH = (const uint4*)(g_Xhi + (size_t)m0 * D_DIM);
        #pragma unroll
        for (int i = 0; i < 16; i++) {
            int idx = tid + i * 256;      // 0..4095 (128 rows x 32 quads)
            int row = idx >> 5, kq = idx & 31;
            *(uint4*)(As + row * LDA + kq * 8) = srcH[row * 32 + kq];
        }
    }
    if (tid < 128) { run[tid] = -3.4e38f; cnt[tid] = 0; }
    __syncthreads();

    int buf = 0;
    #pragma unroll 1
    for (int nt128 = 0; nt128 < K_CODES / 128; nt128++) {
        const int n0 = nt128 * 128;
        if (tid < 128) csqs[tid] = g_csq[n0 + tid];

        float acc[2][8][4];
        #pragma unroll
        for (int a = 0; a < 2; a++)
            #pragma unroll
            for (int b = 0; b < 8; b++)
                #pragma unroll
                for (int c = 0; c < 4; c++) acc[a][b][c] = 0.f;

        #pragma unroll 1
        for (int kc = 0; kc < 4; kc++) {          // k chunks of 64
            // Issue prefetch of the next chunk into the other buffer.
            bool last = (nt128 == K_CODES / 128 - 1) && (kc == 3);
            if (!last) {
                int nn0  = (kc == 3) ? n0 + 128 : n0;
                int nkb  = (kc == 3) ? 0 : (kc + 1) * 64;
                load_B_chunk(sB + (buf ^ 1) * B_BUF, nn0, nkb, tid);
                asm volatile("cp.async.commit_group;");
                asm volatile("cp.async.wait_group 1;");
            } else {
                asm volatile("cp.async.wait_group 0;");
            }
            __syncthreads();

            const unsigned bufB = sB + buf * B_BUF;
            #pragma unroll
            for (int ks = 0; ks < 4; ks++) {      // k16 steps inside chunk
                unsigned ah[2][4];
                #pragma unroll
                for (int mi = 0; mi < 2; mi++) {
                    int arow = wm * 32 + mi * 16 + (lane & 15);
                    int acol = kc * 64 + ks * 16 + (lane >> 4) * 8;
                    ldsm4(su32(As + arow * LDA + acol),
                          ah[mi][0], ah[mi][1], ah[mi][2], ah[mi][3]);
                }
                #pragma unroll
                for (int nb = 0; nb < 4; nb++) {
                    int brow = wn * 64 + nb * 16 + (lane >> 4) * 8 + (lane & 7);
                    int bcol = ks * 16 + ((lane >> 3) & 1) * 8;
                    unsigned b0, b1, b2, b3;
                    ldsm4(bufB + (brow * LDB + bcol) * 2, b0, b1, b2, b3);
                    #pragma unroll
                    for (int mi = 0; mi < 2; mi++) {
                        mma16816(acc[mi][nb * 2],     ah[mi], b0, b1);
                        mma16816(acc[mi][nb * 2 + 1], ah[mi], b2, b3);
                    }
                }
            }
            __syncthreads();
            buf ^= 1;
        }

        // ---- Epilogue part 1: per-row max over this tile's 128 codes ----
        #pragma unroll
        for (int mi = 0; mi < 2; mi++) {
            #pragma unroll
            for (int rh = 0; rh < 2; rh++) {
                float mx = -3.4e38f;
                #pragma unroll
                for (int nt = 0; nt < 8; nt++) {
                    #pragma unroll
                    for (int c = 0; c < 2; c++) {
                        int col = wn * 64 + nt * 8 + (lane & 3) * 2 + c;
                        float s = acc[mi][nt][rh * 2 + c] - 0.5f * csqs[col];
                        mx = fmaxf(mx, s);
                    }
                }
                #pragma unroll
                for (int m = 1; m <= 2; m <<= 1)
                    mx = fmaxf(mx, __shfl_xor_sync(0xffffffffu, mx, m));
                if ((lane & 3) == 0) {
                    int r = wm * 32 + mi * 16 + rh * 8 + (lane >> 2);
                    stage[wn * 128 + r] = mx;
                }
            }
        }
        __syncthreads();
        if (tid < 128)
            run[tid] = fmaxf(run[tid], fmaxf(stage[tid], stage[128 + tid]));
        __syncthreads();

        // ---- Epilogue part 2: append candidates within MARGIN of run max --
        #pragma unroll
        for (int mi = 0; mi < 2; mi++) {
            #pragma unroll
            for (int rh = 0; rh < 2; rh++) {
                int r = wm * 32 + mi * 16 + rh * 8 + (lane >> 2);
                float thresh = run[r] - MARGIN;
                #pragma unroll
                for (int nt = 0; nt < 8; nt++) {
                    #pragma unroll
                    for (int c = 0; c < 2; c++) {
                        int col = wn * 64 + nt * 8 + (lane & 3) * 2 + c;
                        float s = acc[mi][nt][rh * 2 + c] - 0.5f * csqs[col];
                        if (s >= thresh) {
                            int slot = atomicAdd(&cnt[r], 1);
                            if (slot < CAP)
                                g_cands[(size_t)(m0 + r) * CAP + slot] = n0 + col;
                        }
                    }
                }
            }
        }
        __syncthreads();
    }

    if (tid < 128) g_candcnt[m0 + tid] = min(cnt[tid], CAP);
}

// ---------------- gather: serial-fp32 rescore (reference-exact arithmetic) -
// One warp per row. Lane ci rescores candidate ci with a SERIAL fmaf chain
// over k = 0..255 in natural order (proven bit-exact vs reference in R7/R10),
// then warp-argmax via better().
__global__ void gather_kernel(const float* __restrict__ X,
                              const float* __restrict__ C,
                              float* __restrict__ out) {
    __shared__ float xs[8][D_DIM];
    __shared__ float wsum[8];
    int warp = threadIdx.x >> 5;
    int lane = threadIdx.x & 31;
    int row = blockIdx.x * 8 + warp;

    float lsum = 0.f;
    if (row < N_ROWS) {
        const float4* xr = (const float4*)(X + (size_t)row * D_DIM);
        float4* xsv = (float4*)xs[warp];
        xsv[lane] = xr[lane];
        xsv[lane + 32] = xr[lane + 32];
        __syncwarp();

        int ncand = g_candcnt[row];
        float bs = -3.4e38f;
        int bc = 0x7fffffff;
        if (lane < ncand) {
            int cd = g_cands[(size_t)row * CAP + lane];
            const float4* cr = (const float4*)(C + (size_t)cd * D_DIM);
            float d = 0.f;
            #pragma unroll 8
            for (int q = 0; q < D_DIM / 4; q++) {
                float4 cv = __ldg(cr + q);
                const float* xp = &xs[warp][q * 4];
                d = fmaf(xp[0], cv.x, d);
                d = fmaf(xp[1], cv.y, d);
                d = fmaf(xp[2], cv.z, d);
                d = fmaf(xp[3], cv.w, d);
            }
            bs = d - 0.5f * g_csq[cd];
            bc = cd;
        }
        #pragma unroll
        for (int o = 16; o; o >>= 1) {
            float os = __shfl_xor_sync(0xffffffffu, bs, o);
            int   oc = __shfl_xor_sync(0xffffffffu, bc, o);
            if (better(os, oc, bs, bc)) { bs = os; bc = oc; }
        }
        int code = bc;

        const float4* cr = (const float4*)(C + (size_t)code * D_DIM);
        float4* orow = (float4*)(out + (size_t)row * D_DIM);
        #pragma unroll
        for (int h = 0; h < 2; h++) {
            float4 x4 = ((float4*)xs[warp])[lane + h * 32];
            float4 cv = cr[lane + h * 32];
            float4 q;
            float dx = cv.x - x4.x; q.x = x4.x + dx; lsum += dx * dx;
            float dy = cv.y - x4.y; q.y = x4.y + dy; lsum += dy * dy;
            float dz = cv.z - x4.z; q.z = x4.z + dz; lsum += dz * dz;
            float dw = cv.w - x4.w; q.w = x4.w + dw; lsum += dw * dw;
            orow[lane + h * 32] = q;
        }
    }
    #pragma unroll
    for (int o = 16; o; o >>= 1) lsum += __shfl_down_sync(0xffffffffu, lsum, o);
    if (lane == 0) wsum[warp] = lsum;
    __syncthreads();
    if (threadIdx.x == 0) {
        float s = 0.f;
        #pragma unroll
        for (int i = 0; i < 8; i++) s += wsum[i];
        g_partial[blockIdx.x] = s;
    }
}

// ---------------- final loss reduction ----------------
__global__ void loss_kernel(float* __restrict__ out, int nPartial, int lossPos) {
    __shared__ float sm[256];
    float s = 0.f;
    for (int i = threadIdx.x; i < nPartial; i += 256) s += g_partial[i];
    sm[threadIdx.x] = s;
    __syncthreads();
    for (int o = 128; o; o >>= 1) {
        if (threadIdx.x < o) sm[threadIdx.x] += sm[threadIdx.x + o];
        __syncthreads();
    }
    if (threadIdx.x == 0)
        out[lossPos] = 1.25f * sm[0] / (float)((long long)N_ROWS * D_DIM);
}

extern "C" void kernel_launch(void* const* d_in, const int* in_sizes, int n_in,
                              void* d_out, int out_size) {
    const float* X = (const float*)d_in[0];   // (16, 2048, 256) fp32
    const float* C = (const float*)d_in[1];   // (4096, 256) fp32
    float* out = (float*)d_out;

    cudaFuncSetAttribute(score_kernel,
                         cudaFuncAttributeMaxDynamicSharedMemorySize, SMEM_TOTAL);

    cvt_x_kernel<<<(N_ROWS * D_DIM / 4 + 255) / 256, 256>>>(X);
    cvt_c_kernel<<<(K_CODES * D_DIM / 4 + 255) / 256, 256>>>(C);
    csq_kernel<<<(K_CODES * 32 + 255) / 256, 256>>>(C);

    score_kernel<<<N_ROWS / 128, 256, SMEM_TOTAL>>>();

    gather_kernel<<<N_ROWS / 8, 256>>>(X, C, out);
    loss_kernel<<<1, 256>>>(out, N_ROWS / 8, out_size - 1);
}